// round 10
// baseline (speedup 1.0000x reference)
#include <cuda_runtime.h>
#include <math.h>
#include <stdint.h>

#define NN 512
#define EMB 64
#define HID 128
#define G4 512   // 4*HID
#define IN2 128  // 2*EMB

#define SMEM_D 48           // W rows resident in SMEM
#define RREM (HID - SMEM_D) // 80 W rows resident in registers (160 regs)
// dynamic smem floats: sW + sh2(dup pairs) + sg
#define LSTM_SMEM_FLOATS (SMEM_D * G4 + HID * 8 + 4 * G4)
#define LSTM_SMEM_BYTES (LSTM_SMEM_FLOATS * 4)

// ---- scratch (device globals; no allocations allowed) ----
__device__ float g_input_feat[NN * IN2];   // [node][128]
__device__ float g_ihc[NN * G4];           // x@W_ih^T + b_ih + b_hh per node
__device__ int   g_orders[NN * NN];        // [start][step]
__device__ float g_WhhT[HID * G4];         // W_hh transposed [d][j]
__device__ float g_embed[NN * HID];        // mean LSTM output per sequence
__device__ float g_logits[4 * NN];

// packed fp32x2 FMA (Blackwell): acc = a*b + acc, lanewise IEEE fp32
#define FFMA2(acc, a, b) \
    asm("fma.rn.f32x2 %0, %1, %2, %0;" : "+l"(acc) : "l"(a), "l"(b))

// ---------------- Threefry2x32 (JAX-compatible) ----------------
__device__ __forceinline__ uint32_t rotl32(uint32_t x, int d) {
    return (x << d) | (x >> (32 - d));
}

__device__ __forceinline__ void threefry(uint32_t k0, uint32_t k1,
                                         uint32_t& x0, uint32_t& x1) {
    uint32_t ks2 = k0 ^ k1 ^ 0x1BD11BDAu;
    x0 += k0; x1 += k1;
    x0 += x1; x1 = rotl32(x1, 13); x1 ^= x0;
    x0 += x1; x1 = rotl32(x1, 15); x1 ^= x0;
    x0 += x1; x1 = rotl32(x1, 26); x1 ^= x0;
    x0 += x1; x1 = rotl32(x1, 6);  x1 ^= x0;
    x0 += k1; x1 += ks2 + 1u;
    x0 += x1; x1 = rotl32(x1, 17); x1 ^= x0;
    x0 += x1; x1 = rotl32(x1, 29); x1 ^= x0;
    x0 += x1; x1 = rotl32(x1, 16); x1 ^= x0;
    x0 += x1; x1 = rotl32(x1, 24); x1 ^= x0;
    x0 += ks2; x1 += k0 + 2u;
    x0 += x1; x1 = rotl32(x1, 13); x1 ^= x0;
    x0 += x1; x1 = rotl32(x1, 15); x1 ^= x0;
    x0 += x1; x1 = rotl32(x1, 26); x1 ^= x0;
    x0 += x1; x1 = rotl32(x1, 6);  x1 ^= x0;
    x0 += k0; x1 += k1 + 3u;
    x0 += x1; x1 = rotl32(x1, 17); x1 ^= x0;
    x0 += x1; x1 = rotl32(x1, 29); x1 ^= x0;
    x0 += x1; x1 = rotl32(x1, 16); x1 ^= x0;
    x0 += x1; x1 = rotl32(x1, 24); x1 ^= x0;
    x0 += k1; x1 += ks2 + 4u;
    x0 += x1; x1 = rotl32(x1, 13); x1 ^= x0;
    x0 += x1; x1 = rotl32(x1, 15); x1 ^= x0;
    x0 += x1; x1 = rotl32(x1, 26); x1 ^= x0;
    x0 += x1; x1 = rotl32(x1, 6);  x1 ^= x0;
    x0 += ks2; x1 += k0 + 5u;
}

// fast activations (err ~1e-6; recurrence is contractive)
__device__ __forceinline__ float fsig(float x) {
    return __fdividef(1.0f, 1.0f + __expf(-x));
}
__device__ __forceinline__ float ftanh(float x) {
    return __fdividef(2.0f, 1.0f + __expf(-2.0f * x)) - 1.0f;
}
__device__ __forceinline__ float sigf(float x) {  // accurate (non-LSTM paths)
    return 1.0f / (1.0f + expf(-x));
}

// ---------------- Kernel A: node_feat / neigh_feat + W_hh transpose ----------
__global__ void k_embed(const int* __restrict__ tags,
                        const float* __restrict__ adj,
                        const float* __restrict__ W_emb,
                        const float* __restrict__ b_emb,
                        const float* __restrict__ W_hh) {
    int i = blockIdx.x;
    int d = threadIdx.x;  // 64
    __shared__ int stags[NN];
    for (int j = d; j < NN; j += 64) stags[j] = tags[j];
    __syncthreads();
    float nf = W_emb[stags[i] * EMB + d] + b_emb[d];
    float acc = 0.f;
    const float* arow = adj + (size_t)i * NN;
    for (int j = 0; j < NN; j++) {
        if (arow[j] > 0.5f) acc += W_emb[stags[j] * EMB + d];
    }
    g_input_feat[i * IN2 + d] = nf;
    g_input_feat[i * IN2 + EMB + d] = acc + b_emb[d];

    // fused W_hh transpose: 512 blocks x 64 threads x 2 elems = 65536
    int idx = (i * 64 + d) * 2;
#pragma unroll
    for (int c = 0; c < 2; c++) {
        int e = idx + c;                 // e = j*HID + dd
        int j = e >> 7, dd = e & 127;
        g_WhhT[dd * G4 + j] = W_hh[e];
    }
}

// ---------------- Kernel C: per-node input-gate contribution ----------------
__global__ void k_ihc(const float* __restrict__ W_ih,
                      const float* __restrict__ b_ih,
                      const float* __restrict__ b_hh) {
    int node = blockIdx.x;
    int j = threadIdx.x;  // 512
    __shared__ float sx[IN2];
    if (j < IN2) sx[j] = g_input_feat[node * IN2 + j];
    __syncthreads();
    const float* wr = W_ih + j * IN2;
    float acc = 0.f;
#pragma unroll 8
    for (int d = 0; d < IN2; d++) acc += sx[d] * wr[d];
    g_ihc[node * G4 + j] = acc + b_ih[j] + b_hh[j];
}

// ---------------- Kernel D: greedy noisy random-walk orderings ----------------
// Partitionable threefry (bit-exact, verified R5-R8) + exact candidate filter
// (noise in [0.01,0.1) => only i with adj[cur,i] >= max-0.09001 can win).
// This version: mask lives in REGISTERS (each slot single-writer==single-reader),
// cross-warp reduce via smem atomicMax, double-buffered accumulators =>
// 3 syncthreads per step and no serial tid0 loops.
__device__ __forceinline__ float walk_noise1(uint32_t f1, uint32_t f2, int i) {
    const float scale = 0.1f - 0.01f;
    uint32_t a = 0u, b = (uint32_t)i;
    threefry(f1, f2, a, b);
    uint32_t bits = a ^ b;
    float u = __uint_as_float((bits >> 9) | 0x3f800000u) - 1.0f;
    return fmaxf(0.01f, __fadd_rn(__fmul_rn(u, scale), 0.01f));
}

__global__ void __launch_bounds__(256) k_orders(const float* __restrict__ adj) {
    int s = blockIdx.x;
    int tid = threadIdx.x;  // 256
    int lane = tid & 31;
    __shared__ uint32_t fi1[NN], fi2[NN];
    __shared__ uint32_t smax[2];
    __shared__ unsigned long long sbest[2];
    __shared__ int scnt[2];
    __shared__ short slist[NN];

    uint32_t k1 = 0u, k2 = (uint32_t)s;
    threefry(0u, 42u, k1, k2);  // split(key(42), 512)[s]
#pragma unroll
    for (int c = 0; c < 2; c++) {
        int t = tid + c * 256;
        uint32_t f1 = 0u, f2 = (uint32_t)t;
        threefry(k1, k2, f1, f2);
        fi1[t] = f1; fi2[t] = f2;
    }
    if (tid == 0) {
        smax[0] = 0; smax[1] = 0;
        sbest[0] = 0ull; sbest[1] = 0ull;
        scnt[0] = 0; scnt[1] = 0;
        g_orders[s * NN] = s;
    }
    // register-resident visited mask: this thread owns nodes tid and tid+256
    bool mask0 = (tid != s);
    bool mask1 = (tid + 256 != s);
    int cur = s;
    __syncthreads();

    for (int t = 0; t < NN - 1; t++) {
        int p = t & 1;
        const float* arow = adj + (size_t)cur * NN;
        float a0 = arow[tid], a1 = arow[tid + 256];

        // region 1: masked max (adj >= 0, so uint compare == float compare)
        float mx = fmaxf(mask0 ? a0 : -1.f, mask1 ? a1 : -1.f);
#pragma unroll
        for (int off = 16; off > 0; off >>= 1)
            mx = fmaxf(mx, __shfl_xor_sync(0xffffffffu, mx, off));
        if (lane == 0 && mx >= 0.f)
            atomicMax(&smax[p], __float_as_uint(mx));
        __syncthreads();  // sync1

        // region 2: reset NEXT step's buffers (safe: last read of [p^1] was
        // before sync1; next write to [p^1] is after sync2+sync3)
        if (tid == 0) { smax[p ^ 1] = 0; sbest[p ^ 1] = 0ull; scnt[p ^ 1] = 0; }
        float thr2 = __uint_as_float(smax[p]) - 0.09001f;
        bool c0 = mask0 && (a0 >= thr2);
        bool c1 = mask1 && (a1 >= thr2);
        unsigned bal0 = __ballot_sync(0xffffffffu, c0);
        unsigned bal1 = __ballot_sync(0xffffffffu, c1);
        int cnt = __popc(bal0) + __popc(bal1);
        int basee = 0;
        if (lane == 0 && cnt) basee = atomicAdd(&scnt[p], cnt);
        basee = __shfl_sync(0xffffffffu, basee, 0);
        unsigned lmask = (1u << lane) - 1u;
        if (c0) slist[basee + __popc(bal0 & lmask)] = (short)tid;
        if (c1) slist[basee + __popc(bal0) + __popc(bal1 & lmask)] =
            (short)(tid + 256);
        __syncthreads();  // sync2

        // region 3: ciphers only for candidates, then argmax via atomicMax
        int nc = scnt[p];
        uint32_t f1 = fi1[t], f2 = fi2[t];
        unsigned long long key = 0ull;
        if (tid < nc) {
            int i = slist[tid];
            float v = arow[i] + walk_noise1(f1, f2, i);
            key = (((unsigned long long)__float_as_uint(v)) << 32) |
                  (unsigned long long)(unsigned)(NN - 1 - i);
        }
        if (tid + 256 < nc) {
            int i = slist[tid + 256];
            float v = arow[i] + walk_noise1(f1, f2, i);
            unsigned long long kk =
                (((unsigned long long)__float_as_uint(v)) << 32) |
                (unsigned long long)(unsigned)(NN - 1 - i);
            if (kk > key) key = kk;
        }
#pragma unroll
        for (int off = 16; off > 0; off >>= 1) {
            unsigned long long o = __shfl_xor_sync(0xffffffffu, key, off);
            if (o > key) key = o;
        }
        if (lane == 0 && key) atomicMax(&sbest[p], key);
        __syncthreads();  // sync3

        // region 4 (no trailing sync): everyone derives nxt; owner updates its
        // own register mask; tid0 stores the order entry.
        int nxt = (NN - 1) - (int)(unsigned)(sbest[p] & 0xffffffffu);
        if (nxt == tid) mask0 = false;
        if (nxt == tid + 256) mask1 = false;
        if (tid == 0) g_orders[s * NN + t + 1] = nxt;
        cur = nxt;
    }
}

// ---------------- Kernel E: LSTM (4 sequences per block, FFMA2) ----------------
// W_hh^T rows [0,SMEM_D) in SMEM, rows [SMEM_D,128) in registers (160 regs —
// back under the spill line). h stored as duplicated fp32 pairs so the hot loop
// is LDS + fma.rn.f32x2 only. Global prefetch pipelined 2 steps ahead.
__global__ void __launch_bounds__(256) k_lstm() {
    extern __shared__ float smem[];
    float* sW  = smem;                      // [SMEM_D][512]
    float* sh2 = smem + SMEM_D * G4;        // [128][4 dup pairs] = 1024 floats
    float* sg  = sh2 + HID * 8;             // [4][512]

    int bb = blockIdx.x;     // 0..127
    int tid = threadIdx.x;   // 0..255
    int base = bb * 4;
    int j0 = tid * 2;

    // stage SMEM W rows
    {
        const float4* src = (const float4*)g_WhhT;
        float4* dst = (float4*)sW;
        for (int i = tid; i < SMEM_D * G4 / 4; i += 256) dst[i] = src[i];
    }
    // register-resident W tail (this thread's j-pair for rows SMEM_D..127)
    unsigned long long wreg[RREM];
#pragma unroll
    for (int r = 0; r < RREM; r++)
        wreg[r] = *(const unsigned long long*)&g_WhhT[(SMEM_D + r) * G4 + j0];

    for (int i = tid; i < HID * 8; i += 256) sh2[i] = 0.f;

    int dA = tid & 127, bA = tid >> 7, bB = bA + 2;
    float cA = 0.f, cB = 0.f, eA = 0.f, eB = 0.f;

    // software pipeline: acc holds ihc for step t; tmp prefetches t+1;
    // ndB holds node ids for t+1.
    unsigned long long acc[4], tmp[4];
    int ndB[4];
    {
        int nd0[4];
#pragma unroll
        for (int b = 0; b < 4; b++) nd0[b] = g_orders[(base + b) * NN];
#pragma unroll
        for (int b = 0; b < 4; b++)
            acc[b] = *(const unsigned long long*)&g_ihc[nd0[b] * G4 + j0];
#pragma unroll
        for (int b = 0; b < 4; b++) ndB[b] = g_orders[(base + b) * NN + 1];
    }
    __syncthreads();

    for (int t = 0; t < NN; t++) {
        // issue next-step prefetches FIRST: they complete under the GEMM
        if (t + 1 < NN) {
#pragma unroll
            for (int b = 0; b < 4; b++)
                tmp[b] = *(const unsigned long long*)&g_ihc[ndB[b] * G4 + j0];
        }
        if (t + 2 < NN) {
#pragma unroll
            for (int b = 0; b < 4; b++)
                ndB[b] = g_orders[(base + b) * NN + t + 2];
        }

        // ---- recurrent GEMM: gates[b][j0,j0+1] += h[b] @ WhhT ----
#pragma unroll 8
        for (int d = 0; d < SMEM_D; d++) {
            unsigned long long w = *(const unsigned long long*)&sW[d * G4 + j0];
            ulonglong2 h01 = *(const ulonglong2*)&sh2[d * 8];
            ulonglong2 h23 = *(const ulonglong2*)&sh2[d * 8 + 4];
            FFMA2(acc[0], h01.x, w);
            FFMA2(acc[1], h01.y, w);
            FFMA2(acc[2], h23.x, w);
            FFMA2(acc[3], h23.y, w);
        }
#pragma unroll
        for (int r = 0; r < RREM; r++) {
            int d = SMEM_D + r;
            ulonglong2 h01 = *(const ulonglong2*)&sh2[d * 8];
            ulonglong2 h23 = *(const ulonglong2*)&sh2[d * 8 + 4];
            FFMA2(acc[0], h01.x, wreg[r]);
            FFMA2(acc[1], h01.y, wreg[r]);
            FFMA2(acc[2], h23.x, wreg[r]);
            FFMA2(acc[3], h23.y, wreg[r]);
        }
#pragma unroll
        for (int b = 0; b < 4; b++)
            *(unsigned long long*)&sg[b * G4 + j0] = acc[b];
        __syncthreads();

        // ---- activations: this thread owns (bA,dA) and (bB,dA) ----
        {
            const float* sgb = sg + bA * G4;
            float gi = sgb[dA], gf = sgb[128 + dA];
            float gg = sgb[256 + dA], go = sgb[384 + dA];
            cA = fsig(gf) * cA + fsig(gi) * ftanh(gg);
            float h = fsig(go) * ftanh(cA);
            eA += h;
            *(float2*)&sh2[dA * 8 + bA * 2] = make_float2(h, h);
        }
        {
            const float* sgb = sg + bB * G4;
            float gi = sgb[dA], gf = sgb[128 + dA];
            float gg = sgb[256 + dA], go = sgb[384 + dA];
            cB = fsig(gf) * cB + fsig(gi) * ftanh(gg);
            float h = fsig(go) * ftanh(cB);
            eB += h;
            *(float2*)&sh2[dA * 8 + bB * 2] = make_float2(h, h);
        }
        // rotate pipeline
#pragma unroll
        for (int b = 0; b < 4; b++) acc[b] = tmp[b];
        __syncthreads();
    }
    g_embed[(base + bA) * HID + dA] = eA * (1.0f / 512.0f);
    g_embed[(base + bB) * HID + dA] = eB * (1.0f / 512.0f);
}

// ---------------- Kernel F: 4-head MLP -> logits ----------------
__global__ void k_mlp(const float* __restrict__ W1s,
                      const float* __restrict__ b1s,
                      const float* __restrict__ W2s,
                      const float* __restrict__ b2s) {
    int n = blockIdx.x;
    int h = threadIdx.x;  // 128
    __shared__ float se[HID];
    __shared__ float red[128];
    se[h] = g_embed[n * HID + h];
    __syncthreads();
    for (int k = 0; k < 4; k++) {
        const float* W1 = W1s + k * HID * HID;
        float acc = b1s[k * HID + h];
#pragma unroll 8
        for (int d = 0; d < HID; d++) acc += se[d] * W1[d * HID + h];
        float r = fmaxf(acc, 0.f) * W2s[k * HID + h];
        red[h] = r;
        __syncthreads();
        for (int off = 64; off > 0; off >>= 1) {
            if (h < off) red[h] += red[h + off];
            __syncthreads();
        }
        if (h == 0) g_logits[k * NN + n] = red[0] + b2s[k];
        __syncthreads();
    }
}

// ---------------- Kernel G: loss + ensemble output ----------------
__global__ void k_final(const int* __restrict__ label,
                        const float* __restrict__ var_raw,
                        float* __restrict__ out) {
    int n = threadIdx.x;  // 512
    __shared__ float cw[4];
    __shared__ float red[NN];
    if (n < 4) {
        float x = var_raw[n];
        cw[n] = (x > 0.f) ? (x + log1pf(expf(-x))) : log1pf(expf(x));
    }
    __syncthreads();
    if (n == 0) {
        float s = cw[0] + cw[1] + cw[2] + cw[3];
        cw[0] /= s; cw[1] /= s; cw[2] /= s; cw[3] /= s;
    }
    __syncthreads();
    float lab = (float)label[0];
    float y = 0.f, lsum = 0.f;
#pragma unroll
    for (int k = 0; k < 4; k++) {
        float L = g_logits[k * NN + n];
        float ls_pos = (L > 0.f) ? -log1pf(expf(-L)) : (L - log1pf(expf(L)));
        float ls_neg = (L < 0.f) ? -log1pf(expf(L)) : (-L - log1pf(expf(-L)));
        lsum += -(lab * ls_pos + (1.f - lab) * ls_neg);
        y += cw[k] * sigf(L);
    }
    red[n] = lsum;
    __syncthreads();
    for (int off = 256; off > 0; off >>= 1) {
        if (n < off) red[n] += red[n + off];
        __syncthreads();
    }
    if (n == 0) out[0] = red[0] * (1.0f / 512.0f);  // sum_k mean_n
    out[1 + n] = y;
}

// ---------------- launcher ----------------
extern "C" void kernel_launch(void* const* d_in, const int* in_sizes, int n_in,
                              void* d_out, int out_size) {
    const int*   tags    = (const int*)d_in[0];
    const float* adj     = (const float*)d_in[1];
    const int*   label   = (const int*)d_in[2];
    const float* W_emb   = (const float*)d_in[3];
    const float* b_emb   = (const float*)d_in[4];
    const float* W_ih    = (const float*)d_in[5];
    const float* W_hh    = (const float*)d_in[6];
    const float* b_ih    = (const float*)d_in[7];
    const float* b_hh    = (const float*)d_in[8];
    const float* W1s     = (const float*)d_in[9];
    const float* b1s     = (const float*)d_in[10];
    const float* W2s     = (const float*)d_in[11];
    const float* b2s     = (const float*)d_in[12];
    const float* var_raw = (const float*)d_in[13];
    float* out = (float*)d_out;

    cudaFuncSetAttribute(k_lstm, cudaFuncAttributeMaxDynamicSharedMemorySize,
                         LSTM_SMEM_BYTES);

    // order chosen so k_lstm is the 4th launch (ncu's sampled slot)
    k_embed<<<NN, 64>>>(tags, adj, W_emb, b_emb, W_hh);
    k_ihc<<<NN, G4>>>(W_ih, b_ih, b_hh);
    k_orders<<<NN, 256>>>(adj);
    k_lstm<<<NN / 4, 256, LSTM_SMEM_BYTES>>>();
    k_mlp<<<NN, 128>>>(W1s, b1s, W2s, b2s);
    k_final<<<1, NN>>>(label, var_raw, out);
    (void)in_sizes; (void)n_in; (void)out_size;
}